// round 1
// baseline (speedup 1.0000x reference)
#include <cuda_runtime.h>
#include <cstddef>

#define NN 100000
#define DD 128
#define CC 40

// ---------------- scratch (static __device__ globals, no allocation) ----------------
__device__ float g_h[(size_t)NN * DD];     // h = X @ W
__device__ float g_agg[(size_t)NN * DD];   // aggregated messages
__device__ float g_feat[(size_t)NN * DD];  // layer output (input to next layer)
__device__ float g_res[(size_t)NN * DD];   // residual
__device__ float g_dinv[NN];               // deg^{-1/2}
__device__ float g_stats[2 * DD];          // column sum / sumsq
__device__ float g_mu[DD];
__device__ float g_rstd[DD];
__device__ int   g_is64;

// ---------------- helpers ----------------
__device__ __forceinline__ void red_add_f32x4(float* p, float a, float b, float c, float d) {
    asm volatile("red.global.add.v4.f32 [%0], {%1,%2,%3,%4};"
                 :: "l"(p), "f"(a), "f"(b), "f"(c), "f"(d) : "memory");
}

__device__ __forceinline__ int edge_at(const void* edges, long long i) {
    if (g_is64) return (int)((const long long*)edges)[i];
    return ((const int*)edges)[i];
}

// ---------------- dtype detection: int64 vs int32 edge_index ----------------
__global__ void detect_kernel(const void* edges) {
    if (threadIdx.x != 0 || blockIdx.x != 0) return;
    const long long* p = (const long long*)edges;
    int ok = 1;
    for (int i = 0; i < 512; i++) {
        long long v = p[i];
        if (v < 0 || v >= NN) { ok = 0; break; }
    }
    g_is64 = ok;
}

// ---------------- degree / normalization ----------------
__global__ void deg_init_kernel() {
    int i = blockIdx.x * blockDim.x + threadIdx.x;
    if (i < NN) g_dinv[i] = 1.0f;  // self loop
}
__global__ void deg_count_kernel(const void* edges, int E) {
    int e = blockIdx.x * blockDim.x + threadIdx.x;
    if (e >= E) return;
    int d = edge_at(edges, (long long)E + e);
    atomicAdd(&g_dinv[d], 1.0f);
}
__global__ void deg_finish_kernel() {
    int i = blockIdx.x * blockDim.x + threadIdx.x;
    if (i < NN) g_dinv[i] = rsqrtf(g_dinv[i]);
}

// ---------------- GEMM: h = X @ W  (N x 128 @ 128 x 128), epilogue: agg = h * dinv^2 ----------------
#define BM 64
#define BK 32
__global__ __launch_bounds__(256) void gemm128_kernel(const float* __restrict__ X,
                                                      const float* __restrict__ W) {
    __shared__ __align__(16) float Xs[BK][68];    // transposed [k][row], padded
    __shared__ float4 Ws[BK][32];                 // [k][col/4]
    int tid = threadIdx.x;
    int tx = tid & 31;        // col group (4 cols)
    int ty = tid >> 5;        // row group (8 rows)
    int row0 = blockIdx.x * BM;

    float acc[8][4];
#pragma unroll
    for (int i = 0; i < 8; i++)
#pragma unroll
        for (int j = 0; j < 4; j++) acc[i][j] = 0.0f;

    const float4* Wg4 = (const float4*)W;

    for (int k0 = 0; k0 < DD; k0 += BK) {
        // stage X tile (transposed)
        {
            int r = tid >> 2;            // 0..63
            int c4 = (tid & 3) * 8;      // 0,8,16,24
            int rr = row0 + r;
            if (rr >= NN) rr = NN - 1;   // clamp; epilogue guards store
            const float* xp = X + (size_t)rr * DD + k0 + c4;
            float4 v0 = *(const float4*)(xp);
            float4 v1 = *(const float4*)(xp + 4);
            Xs[c4 + 0][r] = v0.x; Xs[c4 + 1][r] = v0.y;
            Xs[c4 + 2][r] = v0.z; Xs[c4 + 3][r] = v0.w;
            Xs[c4 + 4][r] = v1.x; Xs[c4 + 5][r] = v1.y;
            Xs[c4 + 6][r] = v1.z; Xs[c4 + 7][r] = v1.w;
        }
        // stage W tile
        {
            float4* Wsf = &Ws[0][0];
#pragma unroll
            for (int j = 0; j < 4; j++)
                Wsf[tid + j * 256] = Wg4[k0 * 32 + tid + j * 256];
        }
        __syncthreads();

#pragma unroll
        for (int kk = 0; kk < BK; kk++) {
            float4 a0 = *(const float4*)&Xs[kk][ty * 8];
            float4 a1 = *(const float4*)&Xs[kk][ty * 8 + 4];
            float4 b = Ws[kk][tx];
            float av[8] = {a0.x, a0.y, a0.z, a0.w, a1.x, a1.y, a1.z, a1.w};
#pragma unroll
            for (int i = 0; i < 8; i++) {
                acc[i][0] += av[i] * b.x;
                acc[i][1] += av[i] * b.y;
                acc[i][2] += av[i] * b.z;
                acc[i][3] += av[i] * b.w;
            }
        }
        __syncthreads();
    }

    int rbase = row0 + ty * 8;
#pragma unroll
    for (int i = 0; i < 8; i++) {
        int r = rbase + i;
        if (r < NN) {
            float di = g_dinv[r];
            float d2 = di * di;
            float4 hv = make_float4(acc[i][0], acc[i][1], acc[i][2], acc[i][3]);
            *(float4*)&g_h[(size_t)r * DD + tx * 4] = hv;
            float4 av = make_float4(hv.x * d2, hv.y * d2, hv.z * d2, hv.w * d2);
            *(float4*)&g_agg[(size_t)r * DD + tx * 4] = av;
        }
    }
}

// ---------------- edge scatter: agg[dst] += h[src] * dinv[src]*dinv[dst]  (warp per edge) ----------------
__global__ __launch_bounds__(256) void scatter_kernel(const void* edges, int E) {
    int gw = (blockIdx.x * blockDim.x + threadIdx.x) >> 5;
    int lane = threadIdx.x & 31;
    if (gw >= E) return;
    int s = edge_at(edges, gw);
    int d = edge_at(edges, (long long)E + gw);
    float w = g_dinv[s] * g_dinv[d];
    const float4* hs = (const float4*)(g_h + (size_t)s * DD);
    float4 v = hs[lane];
    float* dst = g_agg + (size_t)d * DD + lane * 4;
    red_add_f32x4(dst, v.x * w, v.y * w, v.z * w, v.w * w);
}

// ---------------- BN statistics ----------------
__global__ void zero_stats_kernel() {
    g_stats[threadIdx.x] = 0.0f;
}
__global__ __launch_bounds__(256) void stats_kernel() {
    int tid = threadIdx.x;
    int col = tid & 127;
    int half = tid >> 7;
    float s = 0.0f, q = 0.0f;
    for (int r = blockIdx.x * 2 + half; r < NN; r += gridDim.x * 2) {
        float v = g_agg[(size_t)r * DD + col];
        s += v; q += v * v;
    }
    __shared__ float sh[256], shq[256];
    sh[tid] = s; shq[tid] = q;
    __syncthreads();
    if (half == 0) {
        s += sh[tid + 128]; q += shq[tid + 128];
        atomicAdd(&g_stats[col], s);
        atomicAdd(&g_stats[DD + col], q);
    }
}
__global__ void finalize_stats_kernel() {
    int d = threadIdx.x;
    float inv_n = 1.0f / (float)NN;
    float mu = g_stats[d] * inv_n;
    float var = g_stats[DD + d] * inv_n - mu * mu;
    g_mu[d] = mu;
    g_rstd[d] = rsqrtf(var + 1e-5f);
}

// ---------------- BN + relu + (residual) + l2norm  (warp per row) ----------------
__global__ __launch_bounds__(256) void normalize_kernel(const float* __restrict__ gamma,
                                                        const float* __restrict__ beta,
                                                        int hasRes, int writeRes) {
    int row = (blockIdx.x * blockDim.x + threadIdx.x) >> 5;
    int lane = threadIdx.x & 31;
    if (row >= NN) return;
    float4 a = ((const float4*)(g_agg + (size_t)row * DD))[lane];
    float4 mu = ((const float4*)g_mu)[lane];
    float4 rs = ((const float4*)g_rstd)[lane];
    float4 gm = ((const float4*)gamma)[lane];
    float4 be = ((const float4*)beta)[lane];
    float4 y;
    y.x = fmaxf(0.0f, (a.x - mu.x) * rs.x * gm.x + be.x);
    y.y = fmaxf(0.0f, (a.y - mu.y) * rs.y * gm.y + be.y);
    y.z = fmaxf(0.0f, (a.z - mu.z) * rs.z * gm.z + be.z);
    y.w = fmaxf(0.0f, (a.w - mu.w) * rs.w * gm.w + be.w);
    if (hasRes) {
        float4 r4 = ((const float4*)(g_res + (size_t)row * DD))[lane];
        y.x += r4.x; y.y += r4.y; y.z += r4.z; y.w += r4.w;
    }
    float ss = y.x * y.x + y.y * y.y + y.z * y.z + y.w * y.w;
#pragma unroll
    for (int o = 16; o > 0; o >>= 1) ss += __shfl_xor_sync(0xFFFFFFFFu, ss, o);
    float nrm = sqrtf(ss);
    float inv = 1.0f / fmaxf(nrm, 1e-12f);
    y.x *= inv; y.y *= inv; y.z *= inv; y.w *= inv;
    ((float4*)(g_feat + (size_t)row * DD))[lane] = y;
    if (writeRes) ((float4*)(g_res + (size_t)row * DD))[lane] = y;
}

// ---------------- output GEMM: out = feat @ Wout + bout  (N x 128 @ 128 x 40) ----------------
__global__ __launch_bounds__(128) void out_gemm_kernel(const float* __restrict__ Wout,
                                                       const float* __restrict__ bout,
                                                       float* __restrict__ out) {
    __shared__ float Ws[DD * CC];                 // 20 KB
    __shared__ __align__(16) float Fs[32 * 132];  // 32 rows, padded stride 132
    int tid = threadIdx.x;

    {
        float4* Wsf4 = (float4*)Ws;
        const float4* Wg4 = (const float4*)Wout;
#pragma unroll
        for (int j = 0; j < 10; j++) Wsf4[tid + j * 128] = Wg4[tid + j * 128];
    }
    int row0 = blockIdx.x * 32;
    {
        const float4* Fg4 = (const float4*)(g_feat + (size_t)row0 * DD);
#pragma unroll
        for (int j = 0; j < 8; j++) {
            int idx4 = tid + j * 128;         // 0..1023
            int r = idx4 >> 5;                 // row in tile
            int c4 = idx4 & 31;                // float4 col
            ((float4*)(Fs + r * 132))[c4] = Fg4[idx4];
        }
    }
    __syncthreads();

    int rg = tid >> 2;            // 0..31 (row in tile)
    int cg = (tid & 3) * 10;      // 0,10,20,30
    float acc[10];
#pragma unroll
    for (int j = 0; j < 10; j++) acc[j] = 0.0f;
#pragma unroll
    for (int k = 0; k < DD; k++) {
        float a = Fs[rg * 132 + k];
#pragma unroll
        for (int j = 0; j < 10; j++) acc[j] += a * Ws[k * CC + cg + j];
    }
    int r = row0 + rg;
#pragma unroll
    for (int j = 0; j < 10; j++)
        out[(size_t)r * CC + cg + j] = acc[j] + bout[cg + j];
}

// ---------------- launch ----------------
extern "C" void kernel_launch(void* const* d_in, const int* in_sizes, int n_in,
                              void* d_out, int out_size) {
    const float* x    = (const float*)d_in[0];
    const void*  edges = d_in[1];
    const float* W1   = (const float*)d_in[2];
    const float* W2   = (const float*)d_in[4];
    const float* W3   = (const float*)d_in[6];
    const float* g1   = (const float*)d_in[8];
    const float* be1  = (const float*)d_in[9];
    const float* g2   = (const float*)d_in[10];
    const float* be2  = (const float*)d_in[11];
    const float* g3   = (const float*)d_in[12];
    const float* be3  = (const float*)d_in[13];
    const float* Wout = (const float*)d_in[14];
    const float* bout = (const float*)d_in[15];
    float* out = (float*)d_out;
    int E = in_sizes[1] / 2;

    float* feat = nullptr;
    cudaGetSymbolAddress((void**)&feat, g_feat);

    int nblk = (NN + 255) / 256;
    int gemm_blk = (NN + BM - 1) / BM;
    int scat_blk = (E + 7) / 8;          // warp per edge, 8 warps/block
    int norm_blk = (NN * 32 + 255) / 256;

    detect_kernel<<<1, 1>>>(edges);
    deg_init_kernel<<<nblk, 256>>>();
    deg_count_kernel<<<(E + 255) / 256, 256>>>(edges, E);
    deg_finish_kernel<<<nblk, 256>>>();

    // ---- layer 1 ----
    gemm128_kernel<<<gemm_blk, 256>>>(x, W1);
    scatter_kernel<<<scat_blk, 256>>>(edges, E);
    zero_stats_kernel<<<1, 256>>>();
    stats_kernel<<<512, 256>>>();
    finalize_stats_kernel<<<1, 128>>>();
    normalize_kernel<<<norm_blk, 256>>>(g1, be1, /*hasRes=*/0, /*writeRes=*/1);

    // ---- layer 2 ----
    gemm128_kernel<<<gemm_blk, 256>>>(feat, W2);
    scatter_kernel<<<scat_blk, 256>>>(edges, E);
    zero_stats_kernel<<<1, 256>>>();
    stats_kernel<<<512, 256>>>();
    finalize_stats_kernel<<<1, 128>>>();
    normalize_kernel<<<norm_blk, 256>>>(g2, be2, /*hasRes=*/1, /*writeRes=*/1);

    // ---- layer 3 ----
    gemm128_kernel<<<gemm_blk, 256>>>(feat, W3);
    scatter_kernel<<<scat_blk, 256>>>(edges, E);
    zero_stats_kernel<<<1, 256>>>();
    stats_kernel<<<512, 256>>>();
    finalize_stats_kernel<<<1, 128>>>();
    normalize_kernel<<<norm_blk, 256>>>(g3, be3, /*hasRes=*/1, /*writeRes=*/0);

    // ---- output head ----
    out_gemm_kernel<<<NN / 32, 128>>>(Wout, bout, out);
}